// round 10
// baseline (speedup 1.0000x reference)
#include <cuda_runtime.h>
#include <cuda_fp16.h>
#include <stdint.h>

#define HD 128
#define NN 512
#define NNODE 1024
#define TJ 128
#define NTILE (NN / TJ)
#define WPAD 136  // padded row length in fp16 elements

// ---------------- device scratch (no allocation allowed) ----------------
__device__ __align__(16) float g_P[NNODE * HD];          // h @ We1[:128] + be1
__device__ __align__(16) float g_Q[NNODE * HD];          // h @ We1[128:256]
__device__ __align__(16) __half g_WT[3][HD * WPAD];      // We2^T, Wp1^T, Wv1^T padded row-major fp16

// ---------------- helpers ----------------
__device__ __forceinline__ uint32_t smem_u32(const void* p) {
    uint32_t a;
    asm("{ .reg .u64 t; cvta.to.shared.u64 t, %1; cvt.u32.u64 %0, t; }" : "=r"(a) : "l"(p));
    return a;
}
__device__ __forceinline__ void gbar(int id) {
    asm volatile("bar.sync %0, %1;" :: "r"(id), "r"(256) : "memory");
}
__device__ __forceinline__ void ldsm_x4(uint32_t addr, uint32_t* r) {
    asm volatile("ldmatrix.sync.aligned.m8n8.x4.shared.b16 {%0,%1,%2,%3}, [%4];"
                 : "=r"(r[0]), "=r"(r[1]), "=r"(r[2]), "=r"(r[3]) : "r"(addr));
}
__device__ __forceinline__ void mma16816(float* c, const uint32_t* a, uint32_t b0, uint32_t b1) {
    asm volatile(
        "mma.sync.aligned.m16n8k16.row.col.f32.f16.f16.f32 "
        "{%0,%1,%2,%3}, {%4,%5,%6,%7}, {%8,%9}, {%0,%1,%2,%3};"
        : "+f"(c[0]), "+f"(c[1]), "+f"(c[2]), "+f"(c[3])
        : "r"(a[0]), "r"(a[1]), "r"(a[2]), "r"(a[3]), "r"(b0), "r"(b1));
}
__device__ __forceinline__ void mma16816h(uint32_t* c, const uint32_t* a, uint32_t b0, uint32_t b1) {
    asm volatile(
        "mma.sync.aligned.m16n8k16.row.col.f16.f16.f16.f16 "
        "{%0,%1}, {%2,%3,%4,%5}, {%6,%7}, {%0,%1};"
        : "+r"(c[0]), "+r"(c[1])
        : "r"(a[0]), "r"(a[1]), "r"(a[2]), "r"(a[3]), "r"(b0), "r"(b1));
}
__device__ __forceinline__ float fast_tanh(float x) {
    float y; asm("tanh.approx.f32 %0, %1;" : "=f"(y) : "f"(x)); return y;
}
__device__ __forceinline__ float fast_sigmoid(float x) {
    return fmaf(fast_tanh(0.5f * x), 0.5f, 0.5f);
}
__device__ __forceinline__ float fast_silu(float x) { return x * fast_sigmoid(x); }
__device__ __forceinline__ uint32_t pack_h2(float a, float b) {
    __half2 h = __floats2half2_rn(a, b);
    return *(uint32_t*)&h;
}
__device__ __forceinline__ float2 unpack_h2(uint32_t u) {
    return __half22float2(*(__half2*)&u);
}

// ---------------- merged prep kernel ----------------
__global__ void prep_all(const float* __restrict__ h,
                         const float* __restrict__ We1,
                         const float* __restrict__ be1,
                         const float* __restrict__ We2,
                         const float* __restrict__ Wp1,
                         const float* __restrict__ Wv1) {
    int bid = blockIdx.x;
    int t = threadIdx.x;
    if (bid < NNODE) {
        __shared__ float hs[HD];
        hs[t] = h[bid * HD + t];
        __syncthreads();
        float p = be1[t], q = 0.f;
#pragma unroll 8
        for (int c = 0; c < HD; c++) {
            float hv = hs[c];
            p = fmaf(hv, We1[c * HD + t], p);
            q = fmaf(hv, We1[(HD + c) * HD + t], q);
        }
        g_P[bid * HD + t] = p;
        g_Q[bid * HD + t] = q;
    } else {
        int wid = bid - NNODE;
        const float* src = (wid == 0) ? We2 : (wid == 1) ? Wp1 : Wv1;
        __half* dst = g_WT[wid];
        for (int i = t; i < HD * WPAD; i += HD) {
            int n = i / WPAD, k = i % WPAD;
            float w = (k < HD) ? src[k * HD + n] : 0.f;   // WT[n][k] = W[k][n]
            dst[i] = __float2half_rn(w);
        }
    }
}

// ---------------- SMEM layout (byte offsets) ----------------
#define TB 34816                     // one 128 x WPAD fp16 tile
// two A tiles at [0, TB); weights at 2TB..5TB
#define OFF_W0   (2 * TB)
#define OFF_W1   (3 * TB)
#define OFF_W2   (4 * TB)
#define FB       (5 * TB)            // 174080
#define OFF_PI    (FB + 0)
#define OFF_BE2   (FB + 512)
#define OFF_BP1   (FB + 1024)
#define OFF_BV1   (FB + 1536)
#define OFF_WA    (FB + 2048)
#define OFF_WP2   (FB + 2560)
#define OFF_WV2   (FB + 3072)
#define OFF_WD    (FB + 3584)
#define OFF_WVV   (FB + 4096)
#define OFF_POSI  (FB + 4608)
#define OFF_VELI  (FB + 4624)
#define GBASE     (FB + 4640)
// per-group block (stride GSTRIDE):
//   +0    atts   128f (512B)
//   +512  adot   256f (1024B)
//   +1536 pdot   256f
//   +2560 vdot   256f
//   +3584 magg   512f (2048B)
//   +5632 d2     128f
//   +6144 v2     128f
//   +6656 pdif   384f (1536B)
//   +8192 vdif   384f
#define GSTRIDE   9728
#define OFF_RED   (GBASE + 2 * GSTRIDE)   // 256*6 f = 6144B
#define OFF_NIN   (OFF_RED + 6144)        // 256f
#define OFF_HID   (OFF_NIN + 1024)        // 128f
#define SMEM_BYTES (OFF_HID + 512 + 32)   // ~205920

// ---------------- main kernel: 512 threads, 2 tile-groups, named barriers ----------------
__global__ void __launch_bounds__(512, 1) egnn_main(
    const float* __restrict__ h, const float* __restrict__ pos, const float* __restrict__ vel,
    const float* __restrict__ We1,
    const float* __restrict__ be2, const float* __restrict__ Wa, const float* __restrict__ ba,
    const float* __restrict__ bp1, const float* __restrict__ Wp2,
    const float* __restrict__ bv1, const float* __restrict__ Wv2,
    const float* __restrict__ Wn1, const float* __restrict__ bn1,
    const float* __restrict__ Wn2, const float* __restrict__ bn2,
    float* __restrict__ out)
{
    extern __shared__ __align__(16) char S[];
    const uint32_t SB = smem_u32(S);

    float* Pi    = (float*)(S + OFF_PI);
    float* be2s  = (float*)(S + OFF_BE2);
    float* bp1s  = (float*)(S + OFF_BP1);
    float* bv1s  = (float*)(S + OFF_BV1);
    float* Was   = (float*)(S + OFF_WA);
    float* Wp2s  = (float*)(S + OFF_WP2);
    float* Wv2s  = (float*)(S + OFF_WV2);
    float* Wds   = (float*)(S + OFF_WD);
    float* Wvvs  = (float*)(S + OFF_WVV);
    float* posiv = (float*)(S + OFF_POSI);
    float* veliv = (float*)(S + OFF_VELI);

    const int node = blockIdx.x;
    const int b = node >> 9;
    const int t = threadIdx.x;
    const int gid = t >> 8;       // tile-group 0/1
    const int tl = t & 255;       // thread-in-group
    const int w8 = tl >> 5;       // warp-in-group (0-7)
    const int lane = t & 31;
    const int g = lane >> 2, tg = lane & 3;
    const int mw = w8 & 3;        // m block (32 rows)
    const int nw = w8 >> 2;       // n half (64 cols)
    const int row = tl & 127;     // E1 row
    const int half = tl >> 7;     // E1 k-half
    const int bid = gid + 1;      // named barrier id

    char* G = S + GBASE + gid * GSTRIDE;
    float* atts  = (float*)(G + 0);
    float* adot2 = (float*)(G + 512);
    float* pdot2 = (float*)(G + 1536);
    float* vdot2 = (float*)(G + 2560);
    float* maggg = (float*)(G + 3584);
    float* d2s   = (float*)(G + 5632);
    float* v2s   = (float*)(G + 6144);
    float* pdifs = (float*)(G + 6656);
    float* vdifs = (float*)(G + 8192);

    // ldmatrix per-lane address components
    const int a_r = (lane & 7) + ((lane >> 3) & 1) * 8;
    const int a_c = (lane >> 4) * 8;
    const int b_r = (lane & 7) + ((lane >> 4) & 1) * 8;
    const int b_c = ((lane >> 3) & 1) * 8;

    const uint32_t OFF_Ag = (uint32_t)(gid * TB);
    const uint32_t Aaddr  = SB + OFF_Ag + (uint32_t)(((mw * 32 + a_r) * WPAD + a_c) * 2);
    const uint32_t Bcomp  = (uint32_t)(((nw * 64 + b_r) * WPAD + b_c) * 2);
    const uint32_t B0addr = SB + OFF_W0 + Bcomp;
    const uint32_t B1addr = SB + OFF_W1 + Bcomp;
    const uint32_t B2addr = SB + OFF_W2 + Bcomp;
    const uint32_t PAIRSTEP = (uint32_t)(16 * WPAD * 2);

    // ---- stage 3 weight tiles (pre-padded fp16) into SMEM (all 512 threads) ----
    {
        uint4* d = (uint4*)(S + OFF_W0);
        const uint4* s = (const uint4*)g_WT;
        for (int i = t; i < 3 * TB / 16; i += 512) d[i] = s[i];
    }
    if (t < HD) {
        Pi[t]   = g_P[node * HD + t];
        be2s[t] = be2[t];  bp1s[t] = bp1[t];  bv1s[t] = bv1[t];
        Was[t]  = Wa[t];   Wp2s[t] = Wp2[t];  Wv2s[t] = Wv2[t];
        Wds[t]  = We1[(2 * HD) * HD + t];
        Wvvs[t] = We1[(2 * HD + 1) * HD + t];
    }
    // init both groups' magg (each thread inits its own group's slots)
    maggg[tl] = 0.f; maggg[256 + tl] = 0.f;
    if (t < 3) { posiv[t] = pos[node * 3 + t]; veliv[t] = vel[node * 3 + t]; }
    const float ba0 = ba[0];
    __syncthreads();

    float c0 = 0, c1 = 0, c2 = 0, e0 = 0, e1 = 0, e2 = 0;

    for (int jt = gid; jt < NTILE; jt += 2) {
        // ---- geometry ----
        if (tl < TJ) {
            int gj = (b << 9) + (jt << 7) + tl;
            float dd = 0.f, vv = 0.f;
#pragma unroll
            for (int c = 0; c < 3; c++) {
                float pd = posiv[c] - pos[gj * 3 + c];
                pdifs[tl * 3 + c] = pd; dd = fmaf(pd, pd, dd);
                float vd = veliv[c] - vel[gj * 3 + c];
                vdifs[tl * 3 + c] = vd; vv = fmaf(vd, vd, vv);
            }
            d2s[tl] = dd; v2s[tl] = vv;
        }
        gbar(bid);

        // ---- E1: m = silu(P_i + Q_j + d2*Wd + v2*Wvv) -> fp16 A tile ----
        {
            const float4* q4 = (const float4*)(g_Q + ((size_t)((b << 9) + (jt << 7) + row)) * HD + (half << 6));
            const float dd = d2s[row], vv = v2s[row];
            char* arow = S + OFF_Ag + (size_t)row * WPAD * 2 + (size_t)(half << 6) * 2;
#pragma unroll
            for (int i4 = 0; i4 < 16; i4++) {
                float4 q = q4[i4];
                int k = (half << 6) + (i4 << 2);
                float p0 = fast_silu(fmaf(vv, Wvvs[k + 0], fmaf(dd, Wds[k + 0], Pi[k + 0] + q.x)));
                float p1 = fast_silu(fmaf(vv, Wvvs[k + 1], fmaf(dd, Wds[k + 1], Pi[k + 1] + q.y)));
                float p2 = fast_silu(fmaf(vv, Wvvs[k + 2], fmaf(dd, Wds[k + 2], Pi[k + 2] + q.z)));
                float p3 = fast_silu(fmaf(vv, Wvvs[k + 3], fmaf(dd, Wds[k + 3], Pi[k + 3] + q.w)));
                *(uint2*)(arow + (i4 << 3)) = make_uint2(pack_h2(p0, p1), pack_h2(p2, p3));
            }
        }
        gbar(bid);

        {
        float acc[2][8][4];

        // ========== GEMM1 (fp32 acc): D = m @ We2 ==========
#pragma unroll
        for (int mt = 0; mt < 2; mt++)
#pragma unroll
            for (int nt = 0; nt < 8; nt++)
#pragma unroll
                for (int i = 0; i < 4; i++) acc[mt][nt][i] = 0.f;
#pragma unroll
        for (int ks = 0; ks < 8; ks++) {
            uint32_t a0[4], a1[4];
            ldsm_x4(Aaddr + ks * 32, a0);
            ldsm_x4(Aaddr + PAIRSTEP + ks * 32, a1);
#pragma unroll
            for (int p = 0; p < 4; p++) {
                uint32_t bf[4];
                ldsm_x4(B0addr + p * PAIRSTEP + ks * 32, bf);
                mma16816(acc[0][2 * p],     a0, bf[0], bf[1]);
                mma16816(acc[0][2 * p + 1], a0, bf[2], bf[3]);
                mma16816(acc[1][2 * p],     a1, bf[0], bf[1]);
                mma16816(acc[1][2 * p + 1], a1, bf[2], bf[3]);
            }
        }
        // ---- epilogue 1: m_ij = silu(D + be2); attention row-dots ----
        {
            float ad0[2] = {0.f, 0.f}, ad1[2] = {0.f, 0.f};
#pragma unroll
            for (int mt = 0; mt < 2; mt++)
#pragma unroll
                for (int nt = 0; nt < 8; nt++) {
                    int col = nw * 64 + nt * 8 + 2 * tg;
                    float be0 = be2s[col], be1v = be2s[col + 1];
                    float wa0 = Was[col], wa1 = Was[col + 1];
                    float s0 = fast_silu(acc[mt][nt][0] + be0);
                    float s1 = fast_silu(acc[mt][nt][1] + be1v);
                    float s2 = fast_silu(acc[mt][nt][2] + be0);
                    float s3 = fast_silu(acc[mt][nt][3] + be1v);
                    acc[mt][nt][0] = s0; acc[mt][nt][1] = s1;
                    acc[mt][nt][2] = s2; acc[mt][nt][3] = s3;
                    ad0[mt] = fmaf(s0, wa0, fmaf(s1, wa1, ad0[mt]));
                    ad1[mt] = fmaf(s2, wa0, fmaf(s3, wa1, ad1[mt]));
                }
#pragma unroll
            for (int mt = 0; mt < 2; mt++) {
                ad0[mt] += __shfl_xor_sync(0xffffffffu, ad0[mt], 1);
                ad0[mt] += __shfl_xor_sync(0xffffffffu, ad0[mt], 2);
                ad1[mt] += __shfl_xor_sync(0xffffffffu, ad1[mt], 1);
                ad1[mt] += __shfl_xor_sync(0xffffffffu, ad1[mt], 2);
            }
            if (tg == 0) {
#pragma unroll
                for (int mt = 0; mt < 2; mt++) {
                    adot2[nw * 128 + mw * 32 + mt * 16 + g]     = ad0[mt];
                    adot2[nw * 128 + mw * 32 + mt * 16 + 8 + g] = ad1[mt];
                }
            }
        }
        gbar(bid);   // GEMM1 A reads done; adot ready

        // ---- store m_ij (fp16) into A; compute att ----
#pragma unroll
        for (int mt = 0; mt < 2; mt++) {
            int r0 = mw * 32 + mt * 16 + g;
#pragma unroll
            for (int nt = 0; nt < 8; nt++) {
                int col = nw * 64 + nt * 8 + 2 * tg;
                *(uint32_t*)(S + OFF_Ag + ((size_t)r0 * WPAD + col) * 2) =
                    pack_h2(acc[mt][nt][0], acc[mt][nt][1]);
                *(uint32_t*)(S + OFF_Ag + ((size_t)(r0 + 8) * WPAD + col) * 2) =
                    pack_h2(acc[mt][nt][2], acc[mt][nt][3]);
            }
        }
        if (tl < TJ) atts[tl] = fast_sigmoid(adot2[tl] + adot2[128 + tl] + ba0);
        gbar(bid);   // atts + m_ij tile ready

        // ---- m_agg from fp32 regs ----
        {
            float ca0[8], ca1[8];
#pragma unroll
            for (int nt = 0; nt < 8; nt++) { ca0[nt] = 0.f; ca1[nt] = 0.f; }
#pragma unroll
            for (int mt = 0; mt < 2; mt++) {
                float attL = atts[mw * 32 + mt * 16 + g];
                float attH = atts[mw * 32 + mt * 16 + 8 + g];
#pragma unroll
                for (int nt = 0; nt < 8; nt++) {
                    ca0[nt] = fmaf(attL, acc[mt][nt][0], fmaf(attH, acc[mt][nt][2], ca0[nt]));
                    ca1[nt] = fmaf(attL, acc[mt][nt][1], fmaf(attH, acc[mt][nt][3], ca1[nt]));
                }
            }
#pragma unroll
            for (int nt = 0; nt < 8; nt++) {
                ca0[nt] += __shfl_xor_sync(0xffffffffu, ca0[nt], 4);
                ca0[nt] += __shfl_xor_sync(0xffffffffu, ca0[nt], 8);
                ca0[nt] += __shfl_xor_sync(0xffffffffu, ca0[nt], 16);
                ca1[nt] += __shfl_xor_sync(0xffffffffu, ca1[nt], 4);
                ca1[nt] += __shfl_xor_sync(0xffffffffu, ca1[nt], 8);
                ca1[nt] += __shfl_xor_sync(0xffffffffu, ca1[nt], 16);
            }
            if (g == 0) {
#pragma unroll
                for (int nt = 0; nt < 8; nt++) {
                    int col = nw * 64 + nt * 8 + 2 * tg;
                    maggg[mw * 128 + col]     += ca0[nt];
                    maggg[mw * 128 + col + 1] += ca1[nt];
                }
            }
        }
        }  // release GEMM1 acc registers

        // ========== fused GEMM2+3 (fp16 acc) ==========
        {
        uint32_t accp[2][8][2];
        uint32_t accv[2][8][2];
#pragma unroll
        for (int mt = 0; mt < 2; mt++)
#pragma unroll
            for (int nt = 0; nt < 8; nt++)
#pragma unroll
                for (int i = 0; i < 2; i++) { accp[mt][nt][i] = 0u; accv[mt][nt][i] = 0u; }
#pragma unroll
        for (int ks = 0; ks < 8; ks++) {
            uint32_t a0[4], a1[4];
            ldsm_x4(Aaddr + ks * 32, a0);
            ldsm_x4(Aaddr + PAIRSTEP + ks * 32, a1);
#pragma unroll
            for (int p = 0; p < 4; p++) {
                uint32_t b1f[4], b2f[4];
                ldsm_x4(B1addr + p * PAIRSTEP + ks * 32, b1f);
                ldsm_x4(B2addr + p * PAIRSTEP + ks * 32, b2f);
                mma16816h(accp[0][2 * p],     a0, b1f[0], b1f[1]);
                mma16816h(accp[0][2 * p + 1], a0, b1f[2], b1f[3]);
                mma16816h(accp[1][2 * p],     a1, b1f[0], b1f[1]);
                mma16816h(accp[1][2 * p + 1], a1, b1f[2], b1f[3]);
                mma16816h(accv[0][2 * p],     a0, b2f[0], b2f[1]);
                mma16816h(accv[0][2 * p + 1], a0, b2f[2], b2f[3]);
                mma16816h(accv[1][2 * p],     a1, b2f[0], b2f[1]);
                mma16816h(accv[1][2 * p + 1], a1, b2f[2], b2f[3]);
            }
        }
        // ---- epilogue 2+3: gate, silu, Wp2/Wv2 dots ----
        {
            float pd0[2] = {0.f, 0.f}, pd1[2] = {0.f, 0.f};
            float vd0[2] = {0.f, 0.f}, vd1[2] = {0.f, 0.f};
#pragma unroll
            for (int mt = 0; mt < 2; mt++) {
                float attL = atts[mw * 32 + mt * 16 + g];
                float attH = atts[mw * 32 + mt * 16 + 8 + g];
#pragma unroll
                for (int nt = 0; nt < 8; nt++) {
                    int col = nw * 64 + nt * 8 + 2 * tg;
                    float bp0 = bp1s[col], bp1v = bp1s[col + 1];
                    float wp0 = Wp2s[col], wp1 = Wp2s[col + 1];
                    float bv0 = bv1s[col], bv1v = bv1s[col + 1];
                    float wv0 = Wv2s[col], wv1 = Wv2s[col + 1];
                    float2 pL = unpack_h2(accp[mt][nt][0]);
                    float2 pH = unpack_h2(accp[mt][nt][1]);
                    float2 vL = unpack_h2(accv[mt][nt][0]);
                    float2 vH = unpack_h2(accv[mt][nt][1]);
                    float p0 = fast_silu(fmaf(attL, pL.x, bp0));
                    float p1 = fast_silu(fmaf(attL, pL.y, bp1v));
                    float p2 = fast_silu(fmaf(attH, pH.x, bp0));
                    float p3 = fast_silu(fmaf(attH, pH.y, bp1v));
                    pd0[mt] = fmaf(p0, wp0, fmaf(p1, wp1, pd0[mt]));
                    pd1[mt] = fmaf(p2, wp0, fmaf(p3, wp1, pd1[mt]));
                    float q0 = fast_silu(fmaf(attL, vL.x, bv0));
                    float q1 = fast_silu(fmaf(attL, vL.y, bv1v));
                    float q2 = fast_silu(fmaf(attH, vH.x, bv0));
                    float q3 = fast_silu(fmaf(attH, vH.y, bv1v));
                    vd0[mt] = fmaf(q0, wv0, fmaf(q1, wv1, vd0[mt]));
                    vd1[mt] = fmaf(q2, wv0, fmaf(q3, wv1, vd1[mt]));
                }
            }
#pragma unroll
            for (int mt = 0; mt < 2; mt++) {
                pd0[mt] += __shfl_xor_sync(0xffffffffu, pd0[mt], 1);
                pd0[mt] += __shfl_xor_sync(0xffffffffu, pd0[mt], 2);
                pd1[mt] += __shfl_xor_sync(0xffffffffu, pd1[mt], 1);
                pd1[mt] += __shfl_xor_sync(0xffffffffu, pd1[mt], 2);
                vd0[mt] += __shfl_xor_sync(0xffffffffu, vd0[mt], 1);
                vd0[mt] += __shfl_xor_sync(0xffffffffu, vd0[mt], 2);
                vd1[mt] += __shfl_xor_sync(0xffffffffu, vd1[mt], 1);
                vd1[mt] += __shfl_xor_sync(0xffffffffu, vd1[mt], 2);
            }
            if (tg == 0) {
#pragma unroll
                for (int mt = 0; mt < 2; mt++) {
                    pdot2[nw * 128 + mw * 32 + mt * 16 + g]     = pd0[mt];
                    pdot2[nw * 128 + mw * 32 + mt * 16 + 8 + g] = pd1[mt];
                    vdot2[nw * 128 + mw * 32 + mt * 16 + g]     = vd0[mt];
                    vdot2[nw * 128 + mw * 32 + mt * 16 + 8 + g] = vd1[mt];
                }
            }
        }
        }  // release GEMM2/3 registers
        gbar(bid);   // pdot/vdot complete

        // ---- tanh weights + weighted diff accumulation ----
        if (tl < TJ) {
            float pw = fast_tanh(pdot2[tl] + pdot2[128 + tl]);
            float vw = fast_tanh(vdot2[tl] + vdot2[128 + tl]);
            c0 = fmaf(pdifs[tl * 3 + 0], pw, c0);
            c1 = fmaf(pdifs[tl * 3 + 1], pw, c1);
            c2 = fmaf(pdifs[tl * 3 + 2], pw, c2);
            e0 = fmaf(vdifs[tl * 3 + 0], vw, e0);
            e1 = fmaf(vdifs[tl * 3 + 1], vw, e1);
            e2 = fmaf(vdifs[tl * 3 + 2], vw, e2);
        }
        gbar(bid);   // protect A/pdif/dots for next iteration
    }

    // ---- pos/vel reduction + outputs (both groups' partials) ----
    float* red = (float*)(S + OFF_RED);
    if (tl < TJ) {
        int r = gid * 128 + tl;
        red[r * 6 + 0] = c0; red[r * 6 + 1] = c1; red[r * 6 + 2] = c2;
        red[r * 6 + 3] = e0; red[r * 6 + 4] = e1; red[r * 6 + 5] = e2;
    }
    __syncthreads();
    if (t < 6) {
        int dim = t % 3, which = t / 3;
        float s = 0.f;
        for (int j = 0; j < 256; j++) s += red[j * 6 + which * 3 + dim];
        float base = which ? veliv[dim] : posiv[dim];
        float o = fmaf(s, 1.0f / (float)(NN - 1), base);
        o = fminf(fmaxf(o, -100.f), 100.f);
        out[NNODE * HD + which * NNODE * 3 + node * 3 + dim] = o;
    }

    // ---- node MLP + residual ----
    float* nin = (float*)(S + OFF_NIN);
    float* hid = (float*)(S + OFF_HID);
    if (t < HD) {
        float* mg0 = (float*)(S + GBASE + 3584);
        float* mg1 = (float*)(S + GBASE + GSTRIDE + 3584);
        nin[t]      = h[node * HD + t];
        nin[HD + t] = mg0[t] + mg0[128 + t] + mg0[256 + t] + mg0[384 + t]
                    + mg1[t] + mg1[128 + t] + mg1[256 + t] + mg1[384 + t];
    }
    __syncthreads();
    if (t < HD) {
        float acc2 = bn1[t];
#pragma unroll 8
        for (int c = 0; c < 2 * HD; c++) acc2 = fmaf(nin[c], Wn1[c * HD + t], acc2);
        hid[t] = fast_silu(acc2);
    }
    __syncthreads();
    if (t < HD) {
        float acc2 = bn2[t] + nin[t];
#pragma unroll 8
        for (int c = 0; c < HD; c++) acc2 = fmaf(hid[c], Wn2[c * HD + t], acc2);
        out[node * HD + t] = acc2;
    }
}

// ---------------------------------------------------------------------------
extern "C" void kernel_launch(void* const* d_in, const int* in_sizes, int n_in,
                              void* d_out, int out_size) {
    const float* h   = (const float*)d_in[0];
    const float* pos = (const float*)d_in[1];
    const float* vel = (const float*)d_in[2];
    const float* We1 = (const float*)d_in[3];
    const float* be1 = (const float*)d_in[4];
    const float* We2 = (const float*)d_in[5];
    const float* be2 = (const float*)d_in[6];
    const float* Wa  = (const float*)d_in[7];
    const float* ba  = (const float*)d_in[8];
    const float* Wp1 = (const float*)d_in[9];
    const float* bp1 = (const float*)d_in[10];
    const float* Wp2 = (const float*)d_in[11];
    const float* Wv1 = (const float*)d_in[12];
    const float* bv1 = (const float*)d_in[13];
    const float* Wv2 = (const float*)d_in[14];
    const float* Wn1 = (const float*)d_in[15];
    const float* bn1 = (const float*)d_in[16];
    const float* Wn2 = (const float*)d_in[17];
    const float* bn2 = (const float*)d_in[18];
    float* out = (float*)d_out;

    cudaFuncSetAttribute(egnn_main, cudaFuncAttributeMaxDynamicSharedMemorySize, SMEM_BYTES);

    prep_all<<<NNODE + 3, HD>>>(h, We1, be1, We2, Wp1, Wv1);
    egnn_main<<<NNODE, 512, SMEM_BYTES>>>(h, pos, vel, We1,
                                          be2, Wa, ba,
                                          bp1, Wp2,
                                          bv1, Wv2,
                                          Wn1, bn1, Wn2, bn2, out);
}

// round 14
// speedup vs baseline: 1.0764x; 1.0764x over previous
#include <cuda_runtime.h>
#include <cuda_fp16.h>
#include <stdint.h>

#define HD 128
#define NN 512
#define NNODE 1024
#define TJ 128
#define NTILE (NN / TJ)
#define WPAD 136  // padded row length in fp16 elements

// ---------------- device scratch (no allocation allowed) ----------------
__device__ __align__(16) float g_P[NNODE * HD];          // h @ We1[:128] + be1
__device__ __align__(16) float g_Q[NNODE * HD];          // h @ We1[128:256]
__device__ __align__(16) __half g_WT[3][HD * WPAD];      // We2^T, Wp1^T, Wv1^T padded row-major fp16

// ---------------- helpers ----------------
__device__ __forceinline__ uint32_t smem_u32(const void* p) {
    uint32_t a;
    asm("{ .reg .u64 t; cvta.to.shared.u64 t, %1; cvt.u32.u64 %0, t; }" : "=r"(a) : "l"(p));
    return a;
}
__device__ __forceinline__ void ldsm_x4(uint32_t addr, uint32_t* r) {
    asm volatile("ldmatrix.sync.aligned.m8n8.x4.shared.b16 {%0,%1,%2,%3}, [%4];"
                 : "=r"(r[0]), "=r"(r[1]), "=r"(r[2]), "=r"(r[3]) : "r"(addr));
}
__device__ __forceinline__ void mma16816(float* c, const uint32_t* a, uint32_t b0, uint32_t b1) {
    asm volatile(
        "mma.sync.aligned.m16n8k16.row.col.f32.f16.f16.f32 "
        "{%0,%1,%2,%3}, {%4,%5,%6,%7}, {%8,%9}, {%0,%1,%2,%3};"
        : "+f"(c[0]), "+f"(c[1]), "+f"(c[2]), "+f"(c[3])
        : "r"(a[0]), "r"(a[1]), "r"(a[2]), "r"(a[3]), "r"(b0), "r"(b1));
}
__device__ __forceinline__ void mma16816h(uint32_t* c, const uint32_t* a, uint32_t b0, uint32_t b1) {
    asm volatile(
        "mma.sync.aligned.m16n8k16.row.col.f16.f16.f16.f16 "
        "{%0,%1}, {%2,%3,%4,%5}, {%6,%7}, {%0,%1};"
        : "+r"(c[0]), "+r"(c[1])
        : "r"(a[0]), "r"(a[1]), "r"(a[2]), "r"(a[3]), "r"(b0), "r"(b1));
}
__device__ __forceinline__ float fast_tanh(float x) {
    float y; asm("tanh.approx.f32 %0, %1;" : "=f"(y) : "f"(x)); return y;
}
__device__ __forceinline__ float fast_sigmoid(float x) {
    return fmaf(fast_tanh(0.5f * x), 0.5f, 0.5f);
}
__device__ __forceinline__ float fast_silu(float x) { return x * fast_sigmoid(x); }
__device__ __forceinline__ uint32_t pack_h2(float a, float b) {
    __half2 h = __floats2half2_rn(a, b);
    return *(uint32_t*)&h;
}
__device__ __forceinline__ float2 unpack_h2(uint32_t u) {
    return __half22float2(*(__half2*)&u);
}
// ---- packed f16x2 math ----
#define H2_HALF 0x38003800u  // {0.5h, 0.5h}
__device__ __forceinline__ uint32_t h2_mul(uint32_t a, uint32_t b) {
    uint32_t d; asm("mul.rn.f16x2 %0, %1, %2;" : "=r"(d) : "r"(a), "r"(b)); return d;
}
__device__ __forceinline__ uint32_t h2_fma(uint32_t a, uint32_t b, uint32_t c) {
    uint32_t d; asm("fma.rn.f16x2 %0, %1, %2, %3;" : "=r"(d) : "r"(a), "r"(b), "r"(c)); return d;
}
__device__ __forceinline__ uint32_t h2_tanh(uint32_t a) {
    uint32_t d; asm("tanh.approx.f16x2 %0, %1;" : "=r"(d) : "r"(a)); return d;
}
// silu(x) = x * (0.5*tanh(0.5x) + 0.5), elementwise on a half2
__device__ __forceinline__ uint32_t silu_h2(uint32_t x) {
    uint32_t u = h2_mul(x, H2_HALF);
    uint32_t t = h2_tanh(u);
    uint32_t s = h2_fma(t, H2_HALF, H2_HALF);
    return h2_mul(x, s);
}

// ---------------- merged prep kernel ----------------
__global__ void prep_all(const float* __restrict__ h,
                         const float* __restrict__ We1,
                         const float* __restrict__ be1,
                         const float* __restrict__ We2,
                         const float* __restrict__ Wp1,
                         const float* __restrict__ Wv1) {
    int bid = blockIdx.x;
    int t = threadIdx.x;
    if (bid < NNODE) {
        __shared__ float hs[HD];
        hs[t] = h[bid * HD + t];
        __syncthreads();
        float p = be1[t], q = 0.f;
#pragma unroll 8
        for (int c = 0; c < HD; c++) {
            float hv = hs[c];
            p = fmaf(hv, We1[c * HD + t], p);
            q = fmaf(hv, We1[(HD + c) * HD + t], q);
        }
        g_P[bid * HD + t] = p;
        g_Q[bid * HD + t] = q;
    } else {
        int wid = bid - NNODE;
        const float* src = (wid == 0) ? We2 : (wid == 1) ? Wp1 : Wv1;
        __half* dst = g_WT[wid];
        for (int i = t; i < HD * WPAD; i += HD) {
            int n = i / WPAD, k = i % WPAD;
            float w = (k < HD) ? src[k * HD + n] : 0.f;   // WT[n][k] = W[k][n]
            dst[i] = __float2half_rn(w);
        }
    }
}

// ---------------- SMEM layout (byte offsets) ----------------
#define TB 34816                     // one 128 x WPAD fp16 tile
#define OFF_A    0                   // A (m, then m_ij)
#define OFF_W0   (TB)
#define OFF_W1   (2 * TB)
#define OFF_W2   (3 * TB)
#define FB       (4 * TB)            // 139264
#define OFF_PI    (FB + 0)
#define OFF_BE2   (FB + 512)
#define OFF_WA    (FB + 1024)
#define OFF_WD    (FB + 1536)
#define OFF_WVV   (FB + 2048)
#define OFF_ATT   (FB + 2560)        // 128 f
#define OFF_ADOT  (FB + 3072)        // 256 f
#define OFF_PDOT  (FB + 4096)        // 256 f
#define OFF_VDOT  (FB + 5120)        // 256 f
#define OFF_MAGG4 (FB + 6144)        // 512 f
#define OFF_D2    (FB + 8192)        // 128 f
#define OFF_V2    (FB + 8704)
#define OFF_PDIF  (FB + 9216)        // 384 f
#define OFF_VDIF  (FB + 10752)       // 384 f
#define OFF_POSI  (FB + 12288)
#define OFF_VELI  (FB + 12304)
#define OFF_RED   (FB + 12320)       // 768 f
#define OFF_NIN   (FB + 15392)       // 256 f
#define OFF_HID   (FB + 16416)       // 128 f
#define OFF_BP1H  (FB + 16928)       // 64 u32 (half2 pairs)
#define OFF_WP2H  (FB + 17184)
#define OFF_BV1H  (FB + 17440)
#define OFF_WV2H  (FB + 17696)
#define SMEM_BYTES (FB + 17952)      // 157216

// ---------------- main kernel: 256 threads, warp tiles 32x64 ----------------
__global__ void __launch_bounds__(256, 1) egnn_main(
    const float* __restrict__ h, const float* __restrict__ pos, const float* __restrict__ vel,
    const float* __restrict__ We1,
    const float* __restrict__ be2, const float* __restrict__ Wa, const float* __restrict__ ba,
    const float* __restrict__ bp1, const float* __restrict__ Wp2,
    const float* __restrict__ bv1, const float* __restrict__ Wv2,
    const float* __restrict__ Wn1, const float* __restrict__ bn1,
    const float* __restrict__ Wn2, const float* __restrict__ bn2,
    float* __restrict__ out)
{
    extern __shared__ __align__(16) char S[];
    const uint32_t SB = smem_u32(S);

    float* Pi    = (float*)(S + OFF_PI);
    float* be2s  = (float*)(S + OFF_BE2);
    float* Was   = (float*)(S + OFF_WA);
    float* Wds   = (float*)(S + OFF_WD);
    float* Wvvs  = (float*)(S + OFF_WVV);
    float* atts  = (float*)(S + OFF_ATT);
    float* adot2 = (float*)(S + OFF_ADOT);
    float* pdot2 = (float*)(S + OFF_PDOT);
    float* vdot2 = (float*)(S + OFF_VDOT);
    float* magg4 = (float*)(S + OFF_MAGG4);
    float* d2s   = (float*)(S + OFF_D2);
    float* v2s   = (float*)(S + OFF_V2);
    float* pdifs = (float*)(S + OFF_PDIF);
    float* vdifs = (float*)(S + OFF_VDIF);
    float* posiv = (float*)(S + OFF_POSI);
    float* veliv = (float*)(S + OFF_VELI);
    uint32_t* bp1h = (uint32_t*)(S + OFF_BP1H);
    uint32_t* wp2h = (uint32_t*)(S + OFF_WP2H);
    uint32_t* bv1h = (uint32_t*)(S + OFF_BV1H);
    uint32_t* wv2h = (uint32_t*)(S + OFF_WV2H);

    const int node = blockIdx.x;
    const int b = node >> 9;
    const int t = threadIdx.x;
    const int w = t >> 5;
    const int lane = t & 31;
    const int g = lane >> 2, tg = lane & 3;
    const int mw = w & 3;         // m block (32 rows)
    const int nw = w >> 2;        // n half (64 cols)
    const int row = t & 127;      // E1 row
    const int half = t >> 7;      // E1 k-half

    // ldmatrix per-lane address components
    const int a_r = (lane & 7) + ((lane >> 3) & 1) * 8;
    const int a_c = (lane >> 4) * 8;
    const int b_r = (lane & 7) + ((lane >> 4) & 1) * 8;
    const int b_c = ((lane >> 3) & 1) * 8;

    const uint32_t Aaddr  = SB + OFF_A + (uint32_t)(((mw * 32 + a_r) * WPAD + a_c) * 2);
    const uint32_t Bcomp  = (uint32_t)(((nw * 64 + b_r) * WPAD + b_c) * 2);
    const uint32_t B0addr = SB + OFF_W0 + Bcomp;
    const uint32_t B1addr = SB + OFF_W1 + Bcomp;
    const uint32_t B2addr = SB + OFF_W2 + Bcomp;
    const uint32_t PAIRSTEP = (uint32_t)(16 * WPAD * 2);

    // ---- stage 3 weight tiles (pre-padded fp16) into SMEM ----
    {
        uint4* d = (uint4*)(S + OFF_W0);
        const uint4* s = (const uint4*)g_WT;
        for (int i = t; i < 3 * TB / 16; i += 256) d[i] = s[i];
    }
    if (t < HD) {
        Pi[t]   = g_P[node * HD + t];
        be2s[t] = be2[t];
        Was[t]  = Wa[t];
        Wds[t]  = We1[(2 * HD) * HD + t];
        Wvvs[t] = We1[(2 * HD + 1) * HD + t];
    }
    if (t < 64) {
        bp1h[t] = pack_h2(bp1[2 * t], bp1[2 * t + 1]);
        wp2h[t] = pack_h2(Wp2[2 * t], Wp2[2 * t + 1]);
        bv1h[t] = pack_h2(bv1[2 * t], bv1[2 * t + 1]);
        wv2h[t] = pack_h2(Wv2[2 * t], Wv2[2 * t + 1]);
    }
    if (t < 256) { magg4[t] = 0.f; magg4[256 + t] = 0.f; }
    if (t < 3) { posiv[t] = pos[node * 3 + t]; veliv[t] = vel[node * 3 + t]; }
    const float ba0 = ba[0];

    float c0 = 0, c1 = 0, c2 = 0, e0 = 0, e1 = 0, e2 = 0;

    for (int jt = 0; jt < NTILE; jt++) {
        __syncthreads();

        // ---- geometry ----
        if (t < TJ) {
            int gj = (b << 9) + (jt << 7) + t;
            float dd = 0.f, vv = 0.f;
#pragma unroll
            for (int c = 0; c < 3; c++) {
                float pd = posiv[c] - pos[gj * 3 + c];
                pdifs[t * 3 + c] = pd; dd = fmaf(pd, pd, dd);
                float vd = veliv[c] - vel[gj * 3 + c];
                vdifs[t * 3 + c] = vd; vv = fmaf(vd, vd, vv);
            }
            d2s[t] = dd; v2s[t] = vv;
        }
        __syncthreads();

        // ---- E1: m = silu(P_i + Q_j + d2*Wd + v2*Wvv) -> fp16 A tile ----
        // preact in fp32, silu in packed f16x2 (result stored directly)
        {
            const float4* q4 = (const float4*)(g_Q + ((size_t)((b << 9) + (jt << 7) + row)) * HD + (half << 6));
            const float dd = d2s[row], vv = v2s[row];
            char* arow = S + OFF_A + (size_t)row * WPAD * 2 + (size_t)(half << 6) * 2;
#pragma unroll
            for (int i4 = 0; i4 < 16; i4++) {
                float4 q = q4[i4];
                int k = (half << 6) + (i4 << 2);
                float p0 = fmaf(vv, Wvvs[k + 0], fmaf(dd, Wds[k + 0], Pi[k + 0] + q.x));
                float p1 = fmaf(vv, Wvvs[k + 1], fmaf(dd, Wds[k + 1], Pi[k + 1] + q.y));
                float p2 = fmaf(vv, Wvvs[k + 2], fmaf(dd, Wds[k + 2], Pi[k + 2] + q.z));
                float p3 = fmaf(vv, Wvvs[k + 3], fmaf(dd, Wds[k + 3], Pi[k + 3] + q.w));
                uint32_t s01 = silu_h2(pack_h2(p0, p1));
                uint32_t s23 = silu_h2(pack_h2(p2, p3));
                *(uint2*)(arow + (i4 << 3)) = make_uint2(s01, s23);
            }
        }
        __syncthreads();

        {
        float acc[2][8][4];

        // ========== GEMM1 (fp32 acc): D = m @ We2 ==========
#pragma unroll
        for (int mt = 0; mt < 2; mt++)
#pragma unroll
            for (int nt = 0; nt < 8; nt++)
#pragma unroll
                for (int i = 0; i < 4; i++) acc[mt][nt][i] = 0.f;
#pragma unroll
        for (int ks = 0; ks < 8; ks++) {
            uint32_t a0[4], a1[4];
            ldsm_x4(Aaddr + ks * 32, a0);
            ldsm_x4(Aaddr + PAIRSTEP + ks * 32, a1);
#pragma unroll
            for (int p = 0; p < 4; p++) {
                uint32_t bf[4];
                ldsm_x4(B0addr + p * PAIRSTEP + ks * 32, bf);
                mma16816(acc[0][2 * p],     a0, bf[0], bf[1]);
                mma16816(acc[0][2 * p + 1], a0, bf[2], bf[3]);
                mma16816(acc[1][2 * p],     a1, bf[0], bf[1]);
                mma16816(acc[1][2 * p + 1], a1, bf[2], bf[3]);
            }
        }
        // ---- epilogue 1 (fp32): m_ij = silu(D + be2); attention row-dots ----
        {
            float ad0[2] = {0.f, 0.f}, ad1[2] = {0.f, 0.f};
#pragma unroll
            for (int mt = 0; mt < 2; mt++)
#pragma unroll
                for (int nt = 0; nt < 8; nt++) {
                    int col = nw * 64 + nt * 8 + 2 * tg;
                    float be0 = be2s[col], be1v = be2s[col + 1];
                    float wa0 = Was[col], wa1 = Was[col + 1];
                    float s0 = fast_silu(acc[mt][nt][0] + be0);
                    float s1 = fast_silu(acc[mt][nt][1] + be1v);
                    float s2 = fast_silu(acc[mt][nt][2] + be0);
                    float s3 = fast_silu(acc[mt][nt][3] + be1v);
                    acc[mt][nt][0] = s0; acc[mt][nt][1] = s1;
                    acc[mt][nt][2] = s2; acc[mt][nt][3] = s3;
                    ad0[mt] = fmaf(s0, wa0, fmaf(s1, wa1, ad0[mt]));
                    ad1[mt] = fmaf(s2, wa0, fmaf(s3, wa1, ad1[mt]));
                }
#pragma unroll
            for (int mt = 0; mt < 2; mt++) {
                ad0[mt] += __shfl_xor_sync(0xffffffffu, ad0[mt], 1);
                ad0[mt] += __shfl_xor_sync(0xffffffffu, ad0[mt], 2);
                ad1[mt] += __shfl_xor_sync(0xffffffffu, ad1[mt], 1);
                ad1[mt] += __shfl_xor_sync(0xffffffffu, ad1[mt], 2);
            }
            if (tg == 0) {
#pragma unroll
                for (int mt = 0; mt < 2; mt++) {
                    adot2[nw * 128 + mw * 32 + mt * 16 + g]     = ad0[mt];
                    adot2[nw * 128 + mw * 32 + mt * 16 + 8 + g] = ad1[mt];
                }
            }
        }
        __syncthreads();   // GEMM1 A reads done; adot2 ready

        // ---- store m_ij (fp16) into A; compute att ----
#pragma unroll
        for (int mt = 0; mt < 2; mt++) {
            int r0 = mw * 32 + mt * 16 + g;
#pragma unroll
            for (int nt = 0; nt < 8; nt++) {
                int col = nw * 64 + nt * 8 + 2 * tg;
                *(uint32_t*)(S + OFF_A + ((size_t)r0 * WPAD + col) * 2) =
                    pack_h2(acc[mt][nt][0], acc[mt][nt][1]);
                *(uint32_t*)(S + OFF_A + ((size_t)(r0 + 8) * WPAD + col) * 2) =
                    pack_h2(acc[mt][nt][2], acc[mt][nt][3]);
            }
        }
        if (t < TJ) atts[t] = fast_sigmoid(adot2[t] + adot2[128 + t] + ba0);
        __syncthreads();   // atts + m_ij tile ready

        // ---- m_agg from fp32 regs ----
        {
            float ca0[8], ca1[8];
#pragma unroll
            for (int nt = 0; nt < 8; nt++) { ca0[nt] = 0.f; ca1[nt] = 0.f; }
#pragma unroll
            for (int mt = 0; mt < 2; mt++) {
                float attL = atts[mw * 32 + mt * 16 + g];
                float attH = atts[mw * 32 + mt * 16 + 8 + g];
#pragma unroll
                for (int nt = 0; nt < 8; nt++) {
                    ca0[nt] = fmaf(attL, acc[mt][nt][0], fmaf(attH, acc[mt][nt][2], ca0[nt]));
                    ca1[nt] = fmaf(attL, acc[mt][nt][1], fmaf(attH, acc[mt][nt][3], ca1[nt]));
                }
            }
#pragma unroll
            for (int nt = 0; nt < 8; nt++) {
                ca0[nt] += __shfl_xor_sync(0xffffffffu, ca0[nt], 4);
                ca0[nt] += __shfl_xor_sync(0xffffffffu, ca0[nt], 8);
                ca0[nt] += __shfl_xor_sync(0xffffffffu, ca0[nt], 16);
                ca1[nt] += __shfl_xor_sync(0xffffffffu, ca1[nt], 4);
                ca1[nt] += __shfl_xor_sync(0xffffffffu, ca1[nt], 8);
                ca1[nt] += __shfl_xor_sync(0xffffffffu, ca1[nt], 16);
            }
            if (g == 0) {
#pragma unroll
                for (int nt = 0; nt < 8; nt++) {
                    int col = nw * 64 + nt * 8 + 2 * tg;
                    magg4[mw * 128 + col]     += ca0[nt];
                    magg4[mw * 128 + col + 1] += ca1[nt];
                }
            }
        }
        }  // release GEMM1 acc registers

        // ========== fused GEMM2+3 (fp16 acc) ==========
        {
        uint32_t accp[2][8][2];
        uint32_t accv[2][8][2];
#pragma unroll
        for (int mt = 0; mt < 2; mt++)
#pragma unroll
            for (int nt = 0; nt < 8; nt++)
#pragma unroll
                for (int i = 0; i < 2; i++) { accp[mt][nt][i] = 0u; accv[mt][nt][i] = 0u; }
#pragma unroll
        for (int ks = 0; ks < 8; ks++) {
            uint32_t a0[4], a1[4];
            ldsm_x4(Aaddr + ks * 32, a0);
            ldsm_x4(Aaddr + PAIRSTEP + ks * 32, a1);
#pragma unroll
            for (int p = 0; p < 4; p++) {
                uint32_t b1f[4], b2f[4];
                ldsm_x4(B1addr + p * PAIRSTEP + ks * 32, b1f);
                ldsm_x4(B2addr + p * PAIRSTEP + ks * 32, b2f);
                mma16816h(accp[0][2 * p],     a0, b1f[0], b1f[1]);
                mma16816h(accp[0][2 * p + 1], a0, b1f[2], b1f[3]);
                mma16816h(accp[1][2 * p],     a1, b1f[0], b1f[1]);
                mma16816h(accp[1][2 * p + 1], a1, b1f[2], b1f[3]);
                mma16816h(accv[0][2 * p],     a0, b2f[0], b2f[1]);
                mma16816h(accv[0][2 * p + 1], a0, b2f[2], b2f[3]);
                mma16816h(accv[1][2 * p],     a1, b2f[0], b2f[1]);
                mma16816h(accv[1][2 * p + 1], a1, b2f[2], b2f[3]);
            }
        }
        // ---- epilogue 2+3 (packed f16x2): gate, silu, Wp2/Wv2 dots ----
        {
            uint32_t pdh[2][2], vdh[2][2];
#pragma unroll
            for (int mt = 0; mt < 2; mt++)
#pragma unroll
                for (int i = 0; i < 2; i++) { pdh[mt][i] = 0u; vdh[mt][i] = 0u; }
#pragma unroll
            for (int mt = 0; mt < 2; mt++) {
                float attL = atts[mw * 32 + mt * 16 + g];
                float attH = atts[mw * 32 + mt * 16 + 8 + g];
                uint32_t attL2 = pack_h2(attL, attL);
                uint32_t attH2 = pack_h2(attH, attH);
#pragma unroll
                for (int nt = 0; nt < 8; nt++) {
                    int cp = nw * 32 + nt * 4 + tg;
                    uint32_t bph = bp1h[cp], wph = wp2h[cp];
                    uint32_t bvh = bv1h[cp], wvh = wv2h[cp];
                    uint32_t sp0 = silu_h2(h2_fma(attL2, accp[mt][nt][0], bph));
                    uint32_t sp1 = silu_h2(h2_fma(attH2, accp[mt][nt][1], bph));
                    pdh[mt][0] = h2_fma(sp0, wph, pdh[mt][0]);
                    pdh[mt][1] = h2_fma(sp1, wph, pdh[mt][1]);
                    uint32_t sv0 = silu_h2(h2_fma(attL2, accv[mt][nt][0], bvh));
                    uint32_t sv1 = silu_h2(h2_fma(attH2, accv[mt][nt][1], bvh));
                    vdh[mt][0] = h2_fma(sv0, wvh, vdh[mt][0]);
                    vdh[mt][1] = h2_fma(sv1, wvh, vdh[mt][1]);
                }
            }
            float pd0[2], pd1[2], vd0[2], vd1[2];
#pragma unroll
            for (int mt = 0; mt < 2; mt++) {
                float2 f;
                f = unpack_h2(pdh[mt][0]); pd0[mt] = f.x + f.y;
                f = unpack_h2(pdh[mt][1]); pd1[mt] = f.x + f.y;
                f = unpack_h2(vdh[mt][0]); vd0[mt] = f.x + f.y;
                f = unpack_h2(vdh[mt][1]); vd1[mt] = f.x + f.y;
            }
#pragma unroll
            for (int mt = 0; mt < 2; mt++) {
                pd0[mt] += __shfl_xor_sync(0xffffffffu, pd0[mt], 1);
                pd0[mt] += __shfl_xor_sync(0xffffffffu, pd0[mt], 2);
                pd1[mt] += __shfl_xor_sync(0xffffffffu, pd1[mt], 1);
                pd1[mt] += __shfl_xor_sync(0xffffffffu, pd1[mt], 2);
                vd0[mt] += __shfl_xor_sync(0xffffffffu, vd0[mt], 1);
                vd0[mt] += __shfl_xor_sync(0xffffffffu, vd0[mt], 2);
                vd1[mt] += __shfl_xor_sync(0xffffffffu, vd1[mt], 1);
                vd1[mt] += __shfl_xor_sync(0xffffffffu, vd1[mt], 2);
            }
            if (tg == 0) {
#pragma unroll
                for (int mt = 0; mt < 2; mt++) {
                    pdot2[nw * 128 + mw * 32 + mt * 16 + g]     = pd0[mt];
                    pdot2[nw * 128 + mw * 32 + mt * 16 + 8 + g] = pd1[mt];
                    vdot2[nw * 128 + mw * 32 + mt * 16 + g]     = vd0[mt];
                    vdot2[nw * 128 + mw * 32 + mt * 16 + 8 + g] = vd1[mt];
                }
            }
        }
        }  // release GEMM2/3 registers
        __syncthreads();   // pdot2/vdot2 complete

        // ---- tanh weights + weighted diff accumulation ----
        if (t < TJ) {
            float pw = fast_tanh(pdot2[t] + pdot2[128 + t]);
            float vw = fast_tanh(vdot2[t] + vdot2[128 + t]);
            c0 = fmaf(pdifs[t * 3 + 0], pw, c0);
            c1 = fmaf(pdifs[t * 3 + 1], pw, c1);
            c2 = fmaf(pdifs[t * 3 + 2], pw, c2);
            e0 = fmaf(vdifs[t * 3 + 0], vw, e0);
            e1 = fmaf(vdifs[t * 3 + 1], vw, e1);
            e2 = fmaf(vdifs[t * 3 + 2], vw, e2);
        }
    }
    __syncthreads();

    // ---- pos/vel reduction + outputs ----
    float* red = (float*)(S + OFF_RED);
    if (t < TJ) {
        red[t * 6 + 0] = c0; red[t * 6 + 1] = c1; red[t * 6 + 2] = c2;
        red[t * 6 + 3] = e0; red[t * 6 + 4] = e1; red[t * 6 + 5] = e2;
    }
    __syncthreads();
    if (t < 6) {
        int dim = t % 3, which = t / 3;
        float s = 0.f;
        for (int j = 0; j < TJ; j++) s += red[j * 6 + which * 3 + dim];
        float base = which ? veliv[dim] : posiv[dim];
        float o = fmaf(s, 1.0f / (float)(NN - 1), base);
        o = fminf(fmaxf(o, -100.f), 100.f);
        out[NNODE * HD + which * NNODE * 3 + node * 3 + dim] = o;
    }

    // ---- node MLP + residual ----
    float* nin = (float*)(S + OFF_NIN);
    float* hid = (float*)(S + OFF_HID);
    if (t < HD) {
        nin[t]      = h[node * HD + t];
        nin[HD + t] = magg4[t] + magg4[128 + t] + magg4[256 + t] + magg4[384 + t];
    }
    __syncthreads();
    if (t < HD) {
        float acc2 = bn1[t];
#pragma unroll 8
        for (int c = 0; c < 2 * HD; c++) acc2 = fmaf(nin[c], Wn1[c * HD + t], acc2);
        hid[t] = fast_silu(acc2);
    }
    __syncthreads();
    if (t < HD) {
        float acc2 = bn2[t] + nin[t];
#pragma unroll 8
        for (int c = 0; c < HD; c++) acc2 = fmaf(hid[c], Wn2[c * HD + t], acc2);
        out[node * HD + t] = acc2;
    }
}

// ---------------------------------------------------------------------------
extern "C" void kernel_launch(void* const* d_in, const int* in_sizes, int n_in,
                              void* d_out, int out_size) {
    const float* h   = (const float*)d_in[0];
    const float* pos = (const float*)d_in[1];
    const float* vel = (const float*)d_in[2];
    const float* We1 = (const float*)d_in[3];
    const float* be1 = (const float*)d_in[4];
    const float* We2 = (const float*)d_in[5];
    const float* be2 = (const float*)d_in[6];
    const float* Wa  = (const float*)d_in[7];
    const float* ba  = (const float*)d_in[8];
    const float* Wp1 = (const float*)d_in[9];
    const float* bp1 = (const float*)d_in[10];
    const float* Wp2 = (const float*)d_in[11];
    const float* Wv1 = (const float*)d_in[12];
    const float* bv1 = (const float*)d_in[13];
    const float* Wv2 = (const float*)d_in[14];
    const float* Wn1 = (const float*)d_in[15];
    const float* bn1 = (const float*)d_in[16];
    const float* Wn2 = (const float*)d_in[17];
    const float* bn2 = (const float*)d_in[18];
    float* out = (float*)d_out;

    cudaFuncSetAttribute(egnn_main, cudaFuncAttributeMaxDynamicSharedMemorySize, SMEM_BYTES);

    prep_all<<<NNODE + 3, HD>>>(h, We1, be1, We2, Wp1, Wv1);
    egnn_main<<<NNODE, 256, SMEM_BYTES>>>(h, pos, vel, We1,
                                          be2, Wa, ba,
                                          bp1, Wp2,
                                          bv1, Wv2,
                                          Wn1, bn1, Wn2, bn2, out);
}